// round 14
// baseline (speedup 1.0000x reference)
#include <cuda_runtime.h>
#include <cuda_bf16.h>
#include <math.h>
#include <stdint.h>

#define Nn 131072
#define Bb 4096
#define Ee 512
#define Hh 8
#define Dd 64
#define EE (Ee*Ee)

// ---------------- scratch (device globals; no allocation allowed) ----------------
__device__ __align__(16) __nv_bfloat16 g_AcatH[4*EE], g_AcatL[4*EE];
__device__ __align__(16) __nv_bfloat16 g_BcatH[4*EE], g_BcatL[4*EE];
__device__ __align__(16) __nv_bfloat16 g_scafH[Bb*Ee], g_scafL[Bb*Ee];
__device__ __align__(16) __nv_bfloat16 g_WeffH[4*EE], g_WeffL[4*EE];
__device__ __align__(16) __nv_bfloat16 g_qqH[Bb*Ee], g_qqL[Bb*Ee];
__device__ __align__(16) __nv_bfloat16 g_qhatH[(size_t)Bb*Hh*Ee], g_qhatL[(size_t)Bb*Hh*Ee];
__device__ __align__(16) __nv_bfloat16 g_xwH[(size_t)Bb*Hh*Ee], g_xwL[(size_t)Bb*Hh*Ee];
__device__ __align__(16) __nv_bfloat16 g_pooledH[Bb*Ee], g_pooledL[Bb*Ee];
__device__ __align__(16) float g_beff[3*Ee];
__device__ int   g_segstart[Bb+1];
__device__ __align__(16) float g_outbuf[Bb*Ee];

// ================= helpers =================
__device__ __forceinline__ uint32_t smem_u32(const void* p) {
    uint32_t a;
    asm("{ .reg .u64 t; cvta.to.shared.u64 t, %1; cvt.u32.u64 %0, t; }" : "=r"(a) : "l"(p));
    return a;
}
__device__ __forceinline__ void ldsm4(uint32_t* r, uint32_t addr) {
    asm volatile("ldmatrix.sync.aligned.m8n8.x4.shared.b16 {%0,%1,%2,%3}, [%4];"
        : "=r"(r[0]), "=r"(r[1]), "=r"(r[2]), "=r"(r[3]) : "r"(addr));
}
__device__ __forceinline__ void ldsm4t(uint32_t* r, uint32_t addr) {
    asm volatile("ldmatrix.sync.aligned.m8n8.x4.trans.shared.b16 {%0,%1,%2,%3}, [%4];"
        : "=r"(r[0]), "=r"(r[1]), "=r"(r[2]), "=r"(r[3]) : "r"(addr));
}
__device__ __forceinline__ void mma16816(float* c, const uint32_t* a, const uint32_t* b) {
    asm volatile("mma.sync.aligned.m16n8k16.row.col.f32.bf16.bf16.f32 "
        "{%0,%1,%2,%3}, {%4,%5,%6,%7}, {%8,%9}, {%0,%1,%2,%3};"
        : "+f"(c[0]), "+f"(c[1]), "+f"(c[2]), "+f"(c[3])
        : "r"(a[0]), "r"(a[1]), "r"(a[2]), "r"(a[3]), "r"(b[0]), "r"(b[1]));
}
__device__ __forceinline__ void split4(float4 v, uint2& hi, uint2& lo) {
    __nv_bfloat162 h0 = __floats2bfloat162_rn(v.x, v.y);
    __nv_bfloat162 h1 = __floats2bfloat162_rn(v.z, v.w);
    float2 f0 = __bfloat1622float2(h0);
    float2 f1 = __bfloat1622float2(h1);
    __nv_bfloat162 l0 = __floats2bfloat162_rn(v.x - f0.x, v.y - f0.y);
    __nv_bfloat162 l1 = __floats2bfloat162_rn(v.z - f1.x, v.w - f1.y);
    hi.x = *(uint32_t*)&h0; hi.y = *(uint32_t*)&h1;
    lo.x = *(uint32_t*)&l0; lo.y = *(uint32_t*)&l1;
}
__device__ __forceinline__ void store_split2(__nv_bfloat16* H, __nv_bfloat16* L,
                                             size_t off, float2 v) {
    __nv_bfloat162 h = __floats2bfloat162_rn(v.x, v.y);
    float2 hf = __bfloat1622float2(h);
    __nv_bfloat162 l = __floats2bfloat162_rn(v.x - hf.x, v.y - hf.y);
    *(uint32_t*)&H[off] = *(uint32_t*)&h;
    *(uint32_t*)&L[off] = *(uint32_t*)&l;
}

#define CPA16(dst, src) \
    asm volatile("cp.async.cg.shared.global [%0], [%1], 16;" :: "r"(dst), "l"(src))
#define CPA_COMMIT() asm volatile("cp.async.commit_group;" ::: "memory")
#define CPA_WAIT1()  asm volatile("cp.async.wait_group 1;" ::: "memory")
#define CPA_WAIT0()  asm volatile("cp.async.wait_group 0;" ::: "memory")

// ================= prep: all independent preprocessing in ONE launch ============
__global__ void __launch_bounds__(256) prep(
    const float* __restrict__ ipw, const float* __restrict__ ow,
    const float* __restrict__ wq,  const float* __restrict__ wk,
    const float* __restrict__ wv,  const float* __restrict__ mow,
    const float* __restrict__ scaffold, const int* __restrict__ batch,
    const float* __restrict__ ipb, const float* __restrict__ bq,
    const float* __restrict__ bv,  const float* __restrict__ mob,
    const float* __restrict__ out_b)
{
    int blk = blockIdx.x;
    int tid = threadIdx.x;

    if (blk < 2048) {
        int z = blk >> 8;
        int id = (blk & 255) * 256 + tid;
        const float* src;
        __nv_bfloat16 *dh, *dl;
        size_t off;
        if (z < 3)       { src = ipw + (size_t)z * EE; dh = g_AcatH; dl = g_AcatL; off = (size_t)z * EE; }
        else if (z == 3) { src = ow;                   dh = g_AcatH; dl = g_AcatL; off = (size_t)3 * EE; }
        else {
            const float* s4[4] = {wq, wk, wv, mow};
            src = s4[z - 4]; dh = g_BcatH; dl = g_BcatL; off = (size_t)(z - 4) * EE;
        }
        float4 v = ((const float4*)src)[id];
        uint2 hi, lo;
        split4(v, hi, lo);
        *(uint2*)&dh[off + (size_t)id * 4] = hi;
        *(uint2*)&dl[off + (size_t)id * 4] = lo;
    } else if (blk < 4096) {
        int id = (blk - 2048) * 256 + tid;
        float4 v = ((const float4*)scaffold)[id];
        uint2 hi, lo;
        split4(v, hi, lo);
        *(uint2*)&g_scafH[(size_t)id * 4] = hi;
        *(uint2*)&g_scafL[(size_t)id * 4] = lo;
    } else if (blk < 4608) {
        int n = (blk - 4096) * 256 + tid;
        if (n < Nn) {
            int b = batch[n];
            if (n == 0 || batch[n - 1] != b) g_segstart[b] = n;
        }
        if (n == 0) g_segstart[Bb] = Nn;
    } else {
        int gw = (blk - 4608) * 8 + (tid >> 5);
        int lane = tid & 31;
        int which = gw / Ee, i = gw % Ee;
        const float* rowp;
        const float* vec;
        float add;
        if (which == 0)      { rowp = ipw + (size_t)i * Ee;            vec = bq;  add = ipb[i]; }
        else if (which == 1) { rowp = ipw + (size_t)(2 * Ee + i) * Ee; vec = bv;  add = ipb[2 * Ee + i]; }
        else                 { rowp = ow + (size_t)i * Ee;             vec = mob; add = out_b[i]; }
        float s = 0.f;
#pragma unroll
        for (int k = 0; k < 4; k++) {
            float4 a = ((const float4*)rowp)[lane + 32 * k];
            float4 b4 = ((const float4*)vec)[lane + 32 * k];
            s += a.x * b4.x + a.y * b4.y + a.z * b4.z + a.w * b4.w;
        }
#pragma unroll
        for (int o = 16; o; o >>= 1) s += __shfl_xor_sync(0xffffffffu, s, o);
        if (lane == 0) g_beff[gw] = s + add;
    }
}

// ================= pipelined HMMA GEMM on pre-split bf16 hi/lo =================
#define ROWB 144
#define S_AHI 0
#define S_ALO 18432
#define S_BHI 36864
#define S_BLO 46080
#define STAGE 55296
#define SM2_TOTAL (2*STAGE)

template<bool TRANSB, bool HASBIAS, bool CSPLIT>
__global__ void __launch_bounds__(256, 2)
tcgemm2(const __nv_bfloat16* __restrict__ Ahi, const __nv_bfloat16* __restrict__ Alo,
        const __nv_bfloat16* __restrict__ Bhi, const __nv_bfloat16* __restrict__ Blo,
        float* __restrict__ Cf, __nv_bfloat16* __restrict__ Chi, __nv_bfloat16* __restrict__ Clo,
        const float* __restrict__ bias,
        int K, int lda, int ldb, int ldc,
        long zA, long zB, long zC, int zBias, float alpha)
{
    extern __shared__ __align__(16) char sm[];
    uint32_t sb = smem_u32(sm);

    int z = blockIdx.z;
    Ahi += (size_t)z * zA;  Alo += (size_t)z * zA;
    Bhi += (size_t)z * zB;  Blo += (size_t)z * zB;
    int bm = blockIdx.y * 128;
    int bn = blockIdx.x * 64;
    int tid = threadIdx.x;
    int wid = tid >> 5;
    int lane = tid & 31;
    int wm = wid & 3;
    int wn = wid >> 2;

    int trow = tid >> 3, tkc = tid & 7;
    const __nv_bfloat16* pAh = Ahi + (size_t)(bm + trow) * lda + tkc * 8;
    const __nv_bfloat16* pAl = Alo + (size_t)(bm + trow) * lda + tkc * 8;
    const __nv_bfloat16* pBh;
    const __nv_bfloat16* pBl;
    if (TRANSB) {
        pBh = Bhi + (size_t)(bn + trow) * ldb + tkc * 8;
        pBl = Blo + (size_t)(bn + trow) * ldb + tkc * 8;
    } else {
        pBh = Bhi + (size_t)trow * ldb + bn + tkc * 8;
        pBl = Blo + (size_t)trow * ldb + bn + tkc * 8;
    }
    uint32_t dA = sb + (uint32_t)trow * ROWB + tkc * 16;
    uint32_t dB = sb + S_BHI + (uint32_t)trow * ROWB + tkc * 16;

#define G2_ISSUE(k0, st) do { \
    _Pragma("unroll") \
    for (int i = 0; i < 4; i++) { \
        CPA16(dA + (st) + i * 4608,         pAh + (k0) + (size_t)i * 32 * lda); \
        CPA16(dA + (st) + S_ALO + i * 4608, pAl + (k0) + (size_t)i * 32 * lda); \
    } \
    _Pragma("unroll") \
    for (int i = 0; i < 2; i++) { \
        if (TRANSB) { \
            CPA16(dB + (st) + i * 4608,                   pBh + (k0) + (size_t)i * 32 * ldb); \
            CPA16(dB + (st) + (S_BLO-S_BHI) + i * 4608,   pBl + (k0) + (size_t)i * 32 * ldb); \
        } else { \
            CPA16(dB + (st) + i * 4608,                   pBh + (size_t)((k0) + i * 32) * ldb); \
            CPA16(dB + (st) + (S_BLO-S_BHI) + i * 4608,   pBl + (size_t)((k0) + i * 32) * ldb); \
        } \
    } \
    CPA_COMMIT(); \
} while (0)

    float acc[2][4][4];
#pragma unroll
    for (int i = 0; i < 2; i++)
#pragma unroll
        for (int f = 0; f < 4; f++)
#pragma unroll
            for (int r = 0; r < 4; r++) acc[i][f][r] = 0.f;

    int am = ((lane >> 3) & 1) * 8 + (lane & 7);
    int ak = (lane >> 4) * 8;
    int bnr = ((lane >> 4) & 1) * 8 + (lane & 7);
    int bkc = ((lane >> 3) & 1) * 8;
    int bkr = ((lane >> 3) & 1) * 8 + (lane & 7);
    int bnc = (lane >> 4) * 8;

    const int nch = K / 64;
    G2_ISSUE(0, 0);

    for (int ch = 0; ch < nch; ch++) {
        bool more = (ch + 1 < nch);
        if (more) G2_ISSUE((ch + 1) * 64, ((ch + 1) & 1) * STAGE);
        if (more) CPA_WAIT1(); else CPA_WAIT0();
        __syncthreads();

        uint32_t cur = (uint32_t)(ch & 1) * STAGE;
#pragma unroll
        for (int ks = 0; ks < 4; ks++) {
            int kk = ks * 16;
            uint32_t bh[4][2], bl[4][2];
#pragma unroll
            for (int g = 0; g < 2; g++) {
                uint32_t r[4];
                if (TRANSB) {
                    uint32_t off = cur + S_BHI + (uint32_t)(wn * 32 + g * 16 + bnr) * ROWB + (kk + bkc) * 2;
                    ldsm4(r, sb + off);
                    bh[g*2][0]=r[0]; bh[g*2][1]=r[1]; bh[g*2+1][0]=r[2]; bh[g*2+1][1]=r[3];
                    ldsm4(r, sb + off + (S_BLO - S_BHI));
                    bl[g*2][0]=r[0]; bl[g*2][1]=r[1]; bl[g*2+1][0]=r[2]; bl[g*2+1][1]=r[3];
                } else {
                    uint32_t off = cur + S_BHI + (uint32_t)(kk + bkr) * ROWB + (wn * 32 + g * 16 + bnc) * 2;
                    ldsm4t(r, sb + off);
                    bh[g*2][0]=r[0]; bh[g*2][1]=r[1]; bh[g*2+1][0]=r[2]; bh[g*2+1][1]=r[3];
                    ldsm4t(r, sb + off + (S_BLO - S_BHI));
                    bl[g*2][0]=r[0]; bl[g*2][1]=r[1]; bl[g*2+1][0]=r[2]; bl[g*2+1][1]=r[3];
                }
            }
            uint32_t ah[2][4], al[2][4];
#pragma unroll
            for (int i = 0; i < 2; i++) {
                uint32_t off = cur + (uint32_t)(wm * 32 + i * 16 + am) * ROWB + (kk + ak) * 2;
                ldsm4(ah[i], sb + off);
                ldsm4(al[i], sb + off + S_ALO);
            }
#pragma unroll
            for (int i = 0; i < 2; i++)
#pragma unroll
                for (int f = 0; f < 4; f++) {
                    mma16816(acc[i][f], ah[i], bh[f]);
                    mma16816(acc[i][f], ah[i], bl[f]);
                    mma16816(acc[i][f], al[i], bh[f]);
                }
        }
        __syncthreads();
    }

#pragma unroll
    for (int i = 0; i < 2; i++) {
#pragma unroll
        for (int f = 0; f < 4; f++) {
            int row = bm + wm * 32 + i * 16 + (lane >> 2);
            int col = bn + wn * 32 + f * 8 + (lane & 3) * 2;
            float2 bb = make_float2(0.f, 0.f);
            if (HASBIAS) bb = *(const float2*)&bias[(long)z * zBias + col];
            float2 v0, v1;
            v0.x = alpha * acc[i][f][0] + bb.x;
            v0.y = alpha * acc[i][f][1] + bb.y;
            v1.x = alpha * acc[i][f][2] + bb.x;
            v1.y = alpha * acc[i][f][3] + bb.y;
            size_t o0 = (size_t)z * zC + (size_t)row * ldc + col;
            size_t o1 = (size_t)z * zC + (size_t)(row + 8) * ldc + col;
            if (CSPLIT) {
                store_split2(Chi, Clo, o0, v0);
                store_split2(Chi, Clo, o1, v1);
            } else {
                *(float2*)&Cf[o0] = v0;
                *(float2*)&Cf[o1] = v1;
            }
        }
    }
#undef G2_ISSUE
}

// ================= qhat GEMM: A-resident, n-loop split across 2 blocks =========
#define Q_AHI 0
#define Q_ALO 18432
#define Q_B0  36864
#define Q_BSZ 18432
#define Q_EPI (Q_B0 + 2*Q_BSZ)
#define QH_TOTAL (Q_EPI + 128*66*4)

__global__ void __launch_bounds__(256, 2)
qhat2(const __nv_bfloat16* __restrict__ Ahi, const __nv_bfloat16* __restrict__ Alo,
      const __nv_bfloat16* __restrict__ WkH, const __nv_bfloat16* __restrict__ WkL)
{
    extern __shared__ __align__(16) char sm[];
    uint32_t sb = smem_u32(sm);

    int z = blockIdx.z;
    int bm = blockIdx.y * 128;
    int nt0 = blockIdx.x * 4;
    const __nv_bfloat16* BH = WkH + (size_t)z * Dd * Ee;
    const __nv_bfloat16* BL = WkL + (size_t)z * Dd * Ee;

    int tid = threadIdx.x;
    int lane = tid & 31;
    int wid = tid >> 5;
    int wm = wid & 3;
    int wn = wid >> 2;

    int trow = tid >> 3, tkc = tid & 7;
    {
        const __nv_bfloat16* pAh = Ahi + (size_t)(bm + trow) * Ee + z * Dd + tkc * 8;
        const __nv_bfloat16* pAl = Alo + (size_t)(bm + trow) * Ee + z * Dd + tkc * 8;
        uint32_t dA = sb + (uint32_t)trow * ROWB + tkc * 16;
#pragma unroll
        for (int i = 0; i < 4; i++) {
            CPA16(dA + i * 4608,         pAh + (size_t)i * 32 * Ee);
            CPA16(dA + Q_ALO + i * 4608, pAl + (size_t)i * 32 * Ee);
        }
    }
    const __nv_bfloat16* pBh = BH + (size_t)trow * Ee + tkc * 8;
    const __nv_bfloat16* pBl = BL + (size_t)trow * Ee + tkc * 8;
    uint32_t dB = sb + Q_B0 + (uint32_t)trow * ROWB + tkc * 16;

#define QB_ISSUE(nt, s) do { \
    _Pragma("unroll") \
    for (int i = 0; i < 2; i++) { \
        CPA16(dB + (s) * Q_BSZ + i * 4608,        pBh + (nt) * 64 + (size_t)i * 32 * Ee); \
        CPA16(dB + (s) * Q_BSZ + 9216 + i * 4608, pBl + (nt) * 64 + (size_t)i * 32 * Ee); \
    } \
    CPA_COMMIT(); \
} while (0)

    QB_ISSUE(nt0, 0);
    int am = ((lane >> 3) & 1) * 8 + (lane & 7);
    int ak = (lane >> 4) * 8;
    int bkr = ((lane >> 3) & 1) * 8 + (lane & 7);
    int bnc = (lane >> 4) * 8;
    int gid = lane >> 2, tig = lane & 3;
    float* ep = (float*)(sm + Q_EPI);        // [128][66]

    for (int j = 0; j < 4; j++) {
        int nt = nt0 + j;
        bool more = (j + 1 < 4);
        if (more) QB_ISSUE(nt + 1, (j + 1) & 1);
        if (more) CPA_WAIT1(); else CPA_WAIT0();
        __syncthreads();

        uint32_t bcur = Q_B0 + (uint32_t)(j & 1) * Q_BSZ;
        float acc[2][4][4];
#pragma unroll
        for (int i = 0; i < 2; i++)
#pragma unroll
            for (int f = 0; f < 4; f++)
#pragma unroll
                for (int r = 0; r < 4; r++) acc[i][f][r] = 0.f;

#pragma unroll
        for (int ks = 0; ks < 4; ks++) {
            int kk = ks * 16;
            uint32_t bh[4][2], bl[4][2];
#pragma unroll
            for (int g = 0; g < 2; g++) {
                uint32_t r[4];
                uint32_t off = bcur + (uint32_t)(kk + bkr) * ROWB + (wn * 32 + g * 16 + bnc) * 2;
                ldsm4t(r, sb + off);
                bh[g*2][0]=r[0]; bh[g*2][1]=r[1]; bh[g*2+1][0]=r[2]; bh[g*2+1][1]=r[3];
                ldsm4t(r, sb + off + 9216);
                bl[g*2][0]=r[0]; bl[g*2][1]=r[1]; bl[g*2+1][0]=r[2]; bl[g*2+1][1]=r[3];
            }
            uint32_t ah[2][4], al[2][4];
#pragma unroll
            for (int i = 0; i < 2; i++) {
                uint32_t off = (uint32_t)(wm * 32 + i * 16 + am) * ROWB + (kk + ak) * 2;
                ldsm4(ah[i], sb + off);
                ldsm4(al[i], sb + off + Q_ALO);
            }
#pragma unroll
            for (int i = 0; i < 2; i++)
#pragma unroll
                for (int f = 0; f < 4; f++) {
                    mma16816(acc[i][f], ah[i], bh[f]);
                    mma16816(acc[i][f], ah[i], bl[f]);
                    mma16816(acc[i][f], al[i], bh[f]);
                }
        }

#pragma unroll
        for (int i = 0; i < 2; i++)
#pragma unroll
            for (int f = 0; f < 4; f++) {
                int rl = wm * 32 + i * 16 + gid;
                int cl = wn * 32 + f * 8 + tig * 2;
                ep[rl * 66 + cl]           = acc[i][f][0];
                ep[rl * 66 + cl + 1]       = acc[i][f][1];
                ep[(rl + 8) * 66 + cl]     = acc[i][f][2];
                ep[(rl + 8) * 66 + cl + 1] = acc[i][f][3];
            }
        __syncthreads();
#pragma unroll
        for (int r = 0; r < 16; r++) {
            int rl = wid + 8 * r;
            float2 v = *(float2*)&ep[rl * 66 + lane * 2];
            v.x *= 0.125f;
            v.y *= 0.125f;
            size_t o = (size_t)(bm + rl) * (Hh * Ee) + (size_t)z * Ee + nt * 64 + lane * 2;
            store_split2(g_qhatH, g_qhatL, o, v);
        }
        if (more) __syncthreads();
    }
#undef QB_ISSUE
}

// ================= fused segment attention, HMMA =================
// Partial-sum stage removed: phase-A partials stored as lgp[w][h*33+node]
// (conflict-free both directions); stats sums the 8 warp-partials directly.
#define XROW   1040
#define F_XHI  0
#define F_XLO  33280
#define F_QHI  66560
#define F_QLO  74880
#define F_LGP  83200
// lgp: 8 warps x 264 floats = 8448 B -> next free 91648, align 16 -> 91648
#define F_PHI  91648
#define F_PLO  92160
#define F_STM  92672
#define F_STZ  92704
#define F_STF  92736
#define SMEM_FA 92768

__global__ void __launch_bounds__(256)
fused_attn_kernel(const float* __restrict__ X)
{
    extern __shared__ __align__(16) char fsm[];
    uint32_t sb = smem_u32(fsm);

    int b = blockIdx.x;
    int t = threadIdx.x;
    int w = t >> 5, lane = t & 31;
    int gid = lane >> 2, tig = lane & 3;
    int s0 = g_segstart[b], e0 = g_segstart[b + 1];

    float* stm = (float*)(fsm + F_STM);
    float* stz = (float*)(fsm + F_STZ);
    float* stf = (float*)(fsm + F_STF);
    float* lgp = (float*)(fsm + F_LGP);    // [8][264] : w-major, h*33+node

    {
        const __nv_bfloat16* qh = g_qhatH + (size_t)b * (Hh * Ee);
        const __nv_bfloat16* ql = g_qhatL + (size_t)b * (Hh * Ee);
#pragma unroll
        for (int i = 0; i < 4; i++) {
            int idx = t + 256 * i;
            int which = idx >> 9;
            int j = idx & 511;
            int h = j >> 6, piece = j & 63;
            const __nv_bfloat16* src = (which ? ql : qh) + h * Ee + piece * 8;
            uint32_t dst = sb + (which ? F_QLO : F_QHI) + (uint32_t)h * XROW + piece * 16;
            CPA16(dst, src);
        }
        CPA_COMMIT();
    }
    if (t < 8) { stm[t] = -1e30f; stz[t] = 0.f; }

    int am  = ((lane >> 3) & 1) * 8 + (lane & 7);
    int ak  = (lane >> 4) * 8;
    int bkr = ((lane >> 3) & 1) * 8 + (lane & 7);
    int bnc = (lane >> 4) * 8;
    int qrow = lane & 7;
    int qc8  = (lane >> 3) * 8;

    float acc[4][4];
#pragma unroll
    for (int mt = 0; mt < 4; mt++)
#pragma unroll
        for (int r = 0; r < 4; r++) acc[mt][r] = 0.f;

    for (int base = s0; base < e0; base += 32) {
        int cnt = min(32, e0 - base);

#pragma unroll
        for (int i = 0; i < 16; i++) {
            int flat = t + 256 * i;
            int node = flat >> 7, c4 = flat & 127;
            float4 v = make_float4(0.f, 0.f, 0.f, 0.f);
            if (node < cnt)
                v = *(const float4*)&X[(size_t)(base + node) * Ee + c4 * 4];
            uint2 hi, lo;
            split4(v, hi, lo);
            uint32_t off = (uint32_t)node * XROW + (uint32_t)c4 * 8;
            *(uint2*)(fsm + F_XHI + off) = hi;
            *(uint2*)(fsm + F_XLO + off) = lo;
        }
        CPA_WAIT0();
        __syncthreads();

        // ---- phase A: warp w computes partial logits over k-slice [w*64,+64) ----
        {
            float lg[2][4];
#pragma unroll
            for (int m = 0; m < 2; m++)
#pragma unroll
                for (int r = 0; r < 4; r++) lg[m][r] = 0.f;

            int ks0 = w * 64;
#pragma unroll
            for (int kb = 0; kb < 2; kb++) {
                int kbase = ks0 + kb * 32;
                uint32_t rq[4];
                uint32_t qoff = (uint32_t)qrow * XROW + (uint32_t)(kbase + qc8) * 2;
                uint32_t bqh[2][2], bql[2][2];
                ldsm4(rq, sb + F_QHI + qoff);
                bqh[0][0]=rq[0]; bqh[0][1]=rq[1]; bqh[1][0]=rq[2]; bqh[1][1]=rq[3];
                ldsm4(rq, sb + F_QLO + qoff);
                bql[0][0]=rq[0]; bql[0][1]=rq[1]; bql[1][0]=rq[2]; bql[1][1]=rq[3];
#pragma unroll
                for (int ks = 0; ks < 2; ks++) {
                    int kk = kbase + ks * 16;
                    uint32_t ah[2][4], al[2][4];
#pragma unroll
                    for (int m = 0; m < 2; m++) {
                        uint32_t aoff = (uint32_t)(m * 16 + am) * XROW + (uint32_t)(kk + ak) * 2;
                        ldsm4(ah[m], sb + F_XHI + aoff);
                        ldsm4(al[m], sb + F_XLO + aoff);
                    }
#pragma unroll
                    for (int m = 0; m < 2; m++) {
                        mma16816(lg[m], ah[m], bqh[ks]);
                        mma16816(lg[m], ah[m], bql[ks]);
                        mma16816(lg[m], al[m], bqh[ks]);
                    }
                }
            }
            // store partials as [h*33 + node] within warp's 264-float slab
            float* lp = lgp + w * 264;
#pragma unroll
            for (int m = 0; m < 2; m++) {
                lp[(2 * tig) * 33 + m * 16 + gid]         = lg[m][0];
                lp[(2 * tig + 1) * 33 + m * 16 + gid]     = lg[m][1];
                lp[(2 * tig) * 33 + m * 16 + gid + 8]     = lg[m][2];
                lp[(2 * tig + 1) * 33 + m * 16 + gid + 8] = lg[m][3];
            }
        }
        __syncthreads();

        // ---- stats: warp w handles head w; sum the 8 partials inline ----
        {
            float s = 0.f;
#pragma unroll
            for (int w2 = 0; w2 < 8; w2++) s += lgp[w2 * 264 + w * 33 + lane];
            float v = (lane < cnt) ? s : -1e30f;
            float mx = v;
#pragma unroll
            for (int o = 16; o; o >>= 1) mx = fmaxf(mx, __shfl_xor_sync(0xffffffffu, mx, o));
            float mo = stm[w];
            float mn = fmaxf(mo, mx);
            float p = (lane < cnt) ? __expf(v - mn) : 0.f;
            __nv_bfloat16 ph = __float2bfloat16(p);
            __nv_bfloat16 pl = __float2bfloat16(p - __bfloat162float(ph));
            ((__nv_bfloat16*)(fsm + F_PHI))[lane * 8 + w] = ph;
            ((__nv_bfloat16*)(fsm + F_PLO))[lane * 8 + w] = pl;
            float ssum = p;
#pragma unroll
            for (int o = 16; o; o >>= 1) ssum += __shfl_xor_sync(0xffffffffu, ssum, o);
            if (lane == 0) {
                float f = __expf(mo - mn);
                stf[w] = f;
                stm[w] = mn;
                stz[w] = stz[w] * f + ssum;
            }
        }
        __syncthreads();

        // ---- phase C ----
        {
            float f0 = stf[2 * tig];
            float f1 = stf[2 * tig + 1];
#pragma unroll
            for (int mt = 0; mt < 4; mt++) {
                acc[mt][0] *= f0; acc[mt][1] *= f1;
                acc[mt][2] *= f0; acc[mt][3] *= f1;
            }
            uint32_t rp[4];
            uint32_t bph[2][2], bpl[2][2];
            ldsm4t(rp, sb + F_PHI + (uint32_t)lane * 16);
            bph[0][0]=rp[0]; bph[0][1]=rp[1]; bph[1][0]=rp[2]; bph[1][1]=rp[3];
            ldsm4t(rp, sb + F_PLO + (uint32_t)lane * 16);
            bpl[0][0]=rp[0]; bpl[0][1]=rp[1]; bpl[1][0]=rp[2]; bpl[1][1]=rp[3];

#pragma unroll
            for (int ks = 0; ks < 2; ks++) {
#pragma unroll
                for (int mt = 0; mt < 4; mt++) {
                    uint32_t aoff = (uint32_t)(ks * 16 + bkr) * XROW
                                  + (uint32_t)(w * 64 + mt * 16 + bnc) * 2;
                    uint32_t ra[4], rl[4];
                    ldsm4t(ra, sb + F_XHI + aoff);
                    ldsm4t(rl, sb + F_XLO + aoff);
                    uint32_t ah2[4] = {ra[0], ra[2], ra[1], ra[3]};
                    uint32_t al2[4] = {rl[0], rl[2], rl[1], rl[3]};
                    mma16816(acc[mt], ah2, bph[ks]);
                    mma16816(acc[mt], al2, bph[ks]);
                    mma16816(acc[mt], ah2, bpl[ks]);
                }
            }
        }
        __syncthreads();
    }

    float rz0 = 1.f / stz[2 * tig];
    float rz1 = 1.f / stz[2 * tig + 1];
    float* fxw = (float*)(fsm + F_XHI);
#pragma unroll
    for (int mt = 0; mt < 4; mt++) {
        int col = w * 64 + mt * 16;
        fxw[(2 * tig) * 520 + col + gid]         = acc[mt][0] * rz0;
        fxw[(2 * tig + 1) * 520 + col + gid]     = acc[mt][1] * rz1;
        fxw[(2 * tig) * 520 + col + 8 + gid]     = acc[mt][2] * rz0;
        fxw[(2 * tig + 1) * 520 + col + 8 + gid] = acc[mt][3] * rz1;
    }
    __syncthreads();
#pragma unroll
    for (int i = 0; i < 8; i++) {
        int idx = t + 256 * i;
        int h = idx >> 8, cp = (idx & 255) * 2;
        float2 v = make_float2(fxw[h * 520 + cp], fxw[h * 520 + cp + 1]);
        store_split2(g_xwH, g_xwL, ((size_t)b * Hh + h) * Ee + cp, v);
    }
}

// ---------------- LayerNorm ----------------
__global__ void __launch_bounds__(256) ln_kernel(const float* __restrict__ lng,
                                                 const float* __restrict__ lnb,
                                                 float* __restrict__ out)
{
    int b = blockIdx.x;
    int t = threadIdx.x;
    float v0 = g_outbuf[(long)b * Ee + t];
    float v1 = g_outbuf[(long)b * Ee + t + 256];
    float s = v0 + v1;
    float q = v0 * v0 + v1 * v1;
#pragma unroll
    for (int o = 16; o; o >>= 1) {
        s += __shfl_xor_sync(0xffffffffu, s, o);
        q += __shfl_xor_sync(0xffffffffu, q, o);
    }
    __shared__ float ss[8], qs[8];
    __shared__ float mu_s, r_s;
    int wid = t >> 5, lane = t & 31;
    if (lane == 0) { ss[wid] = s; qs[wid] = q; }
    __syncthreads();
    if (t == 0) {
        float S = 0.f, Q = 0.f;
#pragma unroll
        for (int i = 0; i < 8; i++) { S += ss[i]; Q += qs[i]; }
        float mu = S / (float)Ee;
        float var = Q / (float)Ee - mu * mu;
        mu_s = mu;
        r_s = 1.f / sqrtf(var + 1e-5f);
    }
    __syncthreads();
    float mu = mu_s, r = r_s;
    out[(long)b * Ee + t]       = (v0 - mu) * r * lng[t]       + lnb[t];
    out[(long)b * Ee + t + 256] = (v1 - mu) * r * lng[t + 256] + lnb[t + 256];
}

// ---------------- launch ----------------
extern "C" void kernel_launch(void* const* d_in, const int* in_sizes, int n_in,
                              void* d_out, int out_size)
{
    (void)in_sizes; (void)n_in; (void)out_size;
    const float* X        = (const float*)d_in[0];
    const float* scaffold = (const float*)d_in[1];
    const float* Wq       = (const float*)d_in[2];
    const float* bq       = (const float*)d_in[3];
    const float* Wk       = (const float*)d_in[4];
    const float* Wv       = (const float*)d_in[6];
    const float* bv       = (const float*)d_in[7];
    const float* ipw      = (const float*)d_in[8];
    const float* ipb      = (const float*)d_in[9];
    const float* mow      = (const float*)d_in[10];
    const float* mob      = (const float*)d_in[11];
    const float* ow       = (const float*)d_in[12];
    const float* ob       = (const float*)d_in[13];
    const float* lng      = (const float*)d_in[14];
    const float* lnb      = (const float*)d_in[15];
    const int*   batch    = (const int*)d_in[16];

    void* p;
    cudaGetSymbolAddress(&p, g_AcatH);   __nv_bfloat16* AcatH = (__nv_bfloat16*)p;
    cudaGetSymbolAddress(&p, g_AcatL);   __nv_bfloat16* AcatL = (__nv_bfloat16*)p;
    cudaGetSymbolAddress(&p, g_BcatH);   __nv_bfloat16* BcatH = (__nv_bfloat16*)p;
    cudaGetSymbolAddress(&p, g_BcatL);   __nv_bfloat16* BcatL = (__nv_bfloat16*)p;
    cudaGetSymbolAddress(&p, g_scafH);   __nv_bfloat16* scafH = (__nv_bfloat16*)p;
    cudaGetSymbolAddress(&p, g_scafL);   __nv_bfloat16* scafL = (__nv_bfloat16*)p;
    cudaGetSymbolAddress(&p, g_WeffH);   __nv_bfloat16* WeffH = (__nv_bfloat16*)p;
    cudaGetSymbolAddress(&p, g_WeffL);   __nv_bfloat16* WeffL = (__nv_bfloat16*)p;
    cudaGetSymbolAddress(&p, g_qqH);     __nv_bfloat16* qqH   = (__nv_bfloat16*)p;
    cudaGetSymbolAddress(&p, g_qqL);     __nv_bfloat16* qqL   = (__nv_bfloat16*)p;
    cudaGetSymbolAddress(&p, g_xwH);     __nv_bfloat16* xwH   = (__nv_bfloat16*)p;
    cudaGetSymbolAddress(&p, g_xwL);     __nv_bfloat16* xwL   = (__nv_bfloat16*)p;
    cudaGetSymbolAddress(&p, g_pooledH); __nv_bfloat16* plH   = (__nv_bfloat16*)p;
    cudaGetSymbolAddress(&p, g_pooledL); __nv_bfloat16* plL   = (__nv_bfloat16*)p;
    cudaGetSymbolAddress(&p, g_beff);    float* beff  = (float*)p;
    cudaGetSymbolAddress(&p, g_outbuf);  float* outbuf = (float*)p;

    cudaFuncSetAttribute(tcgemm2<false, false, true>,
                         cudaFuncAttributeMaxDynamicSharedMemorySize, SM2_TOTAL);
    cudaFuncSetAttribute(tcgemm2<true, true, true>,
                         cudaFuncAttributeMaxDynamicSharedMemorySize, SM2_TOTAL);
    cudaFuncSetAttribute(tcgemm2<true, true, false>,
                         cudaFuncAttributeMaxDynamicSharedMemorySize, SM2_TOTAL);
    cudaFuncSetAttribute(qhat2,
                         cudaFuncAttributeMaxDynamicSharedMemorySize, QH_TOTAL);
    cudaFuncSetAttribute(fused_attn_kernel,
                         cudaFuncAttributeMaxDynamicSharedMemorySize, SMEM_FA);

    // ALL independent preprocessing in one launch
    prep<<<4800, 256>>>(ipw, ow, Wq, Wk, Wv, mow, scaffold, batch,
                        ipb, bq, bv, mob, ob);

    // fold: Weff[z] = Acat[z] @ Bcat[z] (NN), write hi/lo
    tcgemm2<false, false, true><<<dim3(8, 4, 4), 256, SM2_TOTAL>>>(
        AcatH, AcatL, BcatH, BcatL, nullptr, WeffH, WeffL, nullptr,
        512, 512, 512, 512, (long)EE, (long)EE, (long)EE, 0, 1.f);

    // qq = scaffold @ Wq_eff^T + bq_eff (NT), write hi/lo
    tcgemm2<true, true, true><<<dim3(8, 32, 1), 256, SM2_TOTAL>>>(
        scafH, scafL, WeffH, WeffL, nullptr, qqH, qqL, beff,
        512, Ee, Ee, Ee, 0, 0, 0, 0, 1.f);

    // qhat (A-resident, n-split x2, pipelined, coalesced epilogue; writes hi/lo)
    qhat2<<<dim3(2, 32, 8), 256, QH_TOTAL>>>(qqH, qqL, WeffH + EE, WeffL + EE);

    fused_attn_kernel<<<Bb, 256, SMEM_FA>>>(X);

    // pooled = xw @ Wv_eff_h^T + bv_eff (NT), write hi/lo
    tcgemm2<true, true, true><<<dim3(1, 32, 8), 256, SM2_TOTAL>>>(
        xwH, xwL, WeffH + 2 * EE, WeffL + 2 * EE, nullptr, plH, plL, beff + Ee,
        512, Hh * Ee, Ee, Ee, (long)Ee, (long)Dd * Ee, (long)Dd, Dd, 1.f);

    // out = pooled @ Wo_eff^T + bo_eff (NT), write fp32
    tcgemm2<true, true, false><<<dim3(8, 32, 1), 256, SM2_TOTAL>>>(
        plH, plL, WeffH + 3 * EE, WeffL + 3 * EE, outbuf, nullptr, nullptr, beff + 2 * Ee,
        512, Ee, Ee, Ee, 0, 0, 0, 0, 1.f);

    ln_kernel<<<Bb, 256>>>(lng, lnb, (float*)d_out);
}

// round 15
// speedup vs baseline: 1.0402x; 1.0402x over previous
#include <cuda_runtime.h>
#include <cuda_bf16.h>
#include <math.h>
#include <stdint.h>

#define Nn 131072
#define Bb 4096
#define Ee 512
#define Hh 8
#define Dd 64
#define EE (Ee*Ee)

// ---------------- scratch (device globals; no allocation allowed) ----------------
__device__ __align__(16) __nv_bfloat16 g_AcatH[4*EE], g_AcatL[4*EE];
__device__ __align__(16) __nv_bfloat16 g_BcatH[4*EE], g_BcatL[4*EE];
__device__ __align__(16) __nv_bfloat16 g_scafH[Bb*Ee], g_scafL[Bb*Ee];
__device__ __align__(16) __nv_bfloat16 g_WeffH[4*EE], g_WeffL[4*EE];
__device__ __align__(16) __nv_bfloat16 g_qqH[Bb*Ee], g_qqL[Bb*Ee];
__device__ __align__(16) __nv_bfloat16 g_qhatH[(size_t)Bb*Hh*Ee], g_qhatL[(size_t)Bb*Hh*Ee];
__device__ __align__(16) __nv_bfloat16 g_xwH[(size_t)Bb*Hh*Ee], g_xwL[(size_t)Bb*Hh*Ee];
__device__ __align__(16) __nv_bfloat16 g_pooledH[Bb*Ee], g_pooledL[Bb*Ee];
__device__ __align__(16) float g_beff[3*Ee];
__device__ int   g_segstart[Bb+1];
__device__ __align__(16) float g_outbuf[Bb*Ee];

// ================= helpers =================
__device__ __forceinline__ uint32_t smem_u32(const void* p) {
    uint32_t a;
    asm("{ .reg .u64 t; cvta.to.shared.u64 t, %1; cvt.u32.u64 %0, t; }" : "=r"(a) : "l"(p));
    return a;
}
__device__ __forceinline__ void ldsm4(uint32_t* r, uint32_t addr) {
    asm volatile("ldmatrix.sync.aligned.m8n8.x4.shared.b16 {%0,%1,%2,%3}, [%4];"
        : "=r"(r[0]), "=r"(r[1]), "=r"(r[2]), "=r"(r[3]) : "r"(addr));
}
__device__ __forceinline__ void ldsm4t(uint32_t* r, uint32_t addr) {
    asm volatile("ldmatrix.sync.aligned.m8n8.x4.trans.shared.b16 {%0,%1,%2,%3}, [%4];"
        : "=r"(r[0]), "=r"(r[1]), "=r"(r[2]), "=r"(r[3]) : "r"(addr));
}
__device__ __forceinline__ void mma16816(float* c, const uint32_t* a, const uint32_t* b) {
    asm volatile("mma.sync.aligned.m16n8k16.row.col.f32.bf16.bf16.f32 "
        "{%0,%1,%2,%3}, {%4,%5,%6,%7}, {%8,%9}, {%0,%1,%2,%3};"
        : "+f"(c[0]), "+f"(c[1]), "+f"(c[2]), "+f"(c[3])
        : "r"(a[0]), "r"(a[1]), "r"(a[2]), "r"(a[3]), "r"(b[0]), "r"(b[1]));
}
__device__ __forceinline__ void split4(float4 v, uint2& hi, uint2& lo) {
    __nv_bfloat162 h0 = __floats2bfloat162_rn(v.x, v.y);
    __nv_bfloat162 h1 = __floats2bfloat162_rn(v.z, v.w);
    float2 f0 = __bfloat1622float2(h0);
    float2 f1 = __bfloat1622float2(h1);
    __nv_bfloat162 l0 = __floats2bfloat162_rn(v.x - f0.x, v.y - f0.y);
    __nv_bfloat162 l1 = __floats2bfloat162_rn(v.z - f1.x, v.w - f1.y);
    hi.x = *(uint32_t*)&h0; hi.y = *(uint32_t*)&h1;
    lo.x = *(uint32_t*)&l0; lo.y = *(uint32_t*)&l1;
}
__device__ __forceinline__ void store_split2(__nv_bfloat16* H, __nv_bfloat16* L,
                                             size_t off, float2 v) {
    __nv_bfloat162 h = __floats2bfloat162_rn(v.x, v.y);
    float2 hf = __bfloat1622float2(h);
    __nv_bfloat162 l = __floats2bfloat162_rn(v.x - hf.x, v.y - hf.y);
    *(uint32_t*)&H[off] = *(uint32_t*)&h;
    *(uint32_t*)&L[off] = *(uint32_t*)&l;
}

#define CPA16(dst, src) \
    asm volatile("cp.async.cg.shared.global [%0], [%1], 16;" :: "r"(dst), "l"(src))
#define CPA_COMMIT() asm volatile("cp.async.commit_group;" ::: "memory")
#define CPA_WAIT1()  asm volatile("cp.async.wait_group 1;" ::: "memory")
#define CPA_WAIT0()  asm volatile("cp.async.wait_group 0;" ::: "memory")

// ================= prep: all independent preprocessing in ONE launch ============
__global__ void __launch_bounds__(256) prep(
    const float* __restrict__ ipw, const float* __restrict__ ow,
    const float* __restrict__ wq,  const float* __restrict__ wk,
    const float* __restrict__ wv,  const float* __restrict__ mow,
    const float* __restrict__ scaffold, const int* __restrict__ batch,
    const float* __restrict__ ipb, const float* __restrict__ bq,
    const float* __restrict__ bv,  const float* __restrict__ mob,
    const float* __restrict__ out_b)
{
    int blk = blockIdx.x;
    int tid = threadIdx.x;

    if (blk < 2048) {
        int z = blk >> 8;
        int id = (blk & 255) * 256 + tid;
        const float* src;
        __nv_bfloat16 *dh, *dl;
        size_t off;
        if (z < 3)       { src = ipw + (size_t)z * EE; dh = g_AcatH; dl = g_AcatL; off = (size_t)z * EE; }
        else if (z == 3) { src = ow;                   dh = g_AcatH; dl = g_AcatL; off = (size_t)3 * EE; }
        else {
            const float* s4[4] = {wq, wk, wv, mow};
            src = s4[z - 4]; dh = g_BcatH; dl = g_BcatL; off = (size_t)(z - 4) * EE;
        }
        float4 v = ((const float4*)src)[id];
        uint2 hi, lo;
        split4(v, hi, lo);
        *(uint2*)&dh[off + (size_t)id * 4] = hi;
        *(uint2*)&dl[off + (size_t)id * 4] = lo;
    } else if (blk < 4096) {
        int id = (blk - 2048) * 256 + tid;
        float4 v = ((const float4*)scaffold)[id];
        uint2 hi, lo;
        split4(v, hi, lo);
        *(uint2*)&g_scafH[(size_t)id * 4] = hi;
        *(uint2*)&g_scafL[(size_t)id * 4] = lo;
    } else if (blk < 4608) {
        int n = (blk - 4096) * 256 + tid;
        if (n < Nn) {
            int b = batch[n];
            if (n == 0 || batch[n - 1] != b) g_segstart[b] = n;
        }
        if (n == 0) g_segstart[Bb] = Nn;
    } else {
        int gw = (blk - 4608) * 8 + (tid >> 5);
        int lane = tid & 31;
        int which = gw / Ee, i = gw % Ee;
        const float* rowp;
        const float* vec;
        float add;
        if (which == 0)      { rowp = ipw + (size_t)i * Ee;            vec = bq;  add = ipb[i]; }
        else if (which == 1) { rowp = ipw + (size_t)(2 * Ee + i) * Ee; vec = bv;  add = ipb[2 * Ee + i]; }
        else                 { rowp = ow + (size_t)i * Ee;             vec = mob; add = out_b[i]; }
        float s = 0.f;
#pragma unroll
        for (int k = 0; k < 4; k++) {
            float4 a = ((const float4*)rowp)[lane + 32 * k];
            float4 b4 = ((const float4*)vec)[lane + 32 * k];
            s += a.x * b4.x + a.y * b4.y + a.z * b4.z + a.w * b4.w;
        }
#pragma unroll
        for (int o = 16; o; o >>= 1) s += __shfl_xor_sync(0xffffffffu, s, o);
        if (lane == 0) g_beff[gw] = s + add;
    }
}

// ================= pipelined HMMA GEMM on pre-split bf16 hi/lo =================
#define ROWB 144
#define S_AHI 0
#define S_ALO 18432
#define S_BHI 36864
#define S_BLO 46080
#define STAGE 55296
#define SM2_TOTAL (2*STAGE)

template<bool TRANSB, bool HASBIAS, bool CSPLIT>
__global__ void __launch_bounds__(256, 2)
tcgemm2(const __nv_bfloat16* __restrict__ Ahi, const __nv_bfloat16* __restrict__ Alo,
        const __nv_bfloat16* __restrict__ Bhi, const __nv_bfloat16* __restrict__ Blo,
        float* __restrict__ Cf, __nv_bfloat16* __restrict__ Chi, __nv_bfloat16* __restrict__ Clo,
        const float* __restrict__ bias,
        int K, int lda, int ldb, int ldc,
        long zA, long zB, long zC, int zBias, float alpha)
{
    extern __shared__ __align__(16) char sm[];
    uint32_t sb = smem_u32(sm);

    int z = blockIdx.z;
    Ahi += (size_t)z * zA;  Alo += (size_t)z * zA;
    Bhi += (size_t)z * zB;  Blo += (size_t)z * zB;
    int bm = blockIdx.y * 128;
    int bn = blockIdx.x * 64;
    int tid = threadIdx.x;
    int wid = tid >> 5;
    int lane = tid & 31;
    int wm = wid & 3;
    int wn = wid >> 2;

    int trow = tid >> 3, tkc = tid & 7;
    const __nv_bfloat16* pAh = Ahi + (size_t)(bm + trow) * lda + tkc * 8;
    const __nv_bfloat16* pAl = Alo + (size_t)(bm + trow) * lda + tkc * 8;
    const __nv_bfloat16* pBh;
    const __nv_bfloat16* pBl;
    if (TRANSB) {
        pBh = Bhi + (size_t)(bn + trow) * ldb + tkc * 8;
        pBl = Blo + (size_t)(bn + trow) * ldb + tkc * 8;
    } else {
        pBh = Bhi + (size_t)trow * ldb + bn + tkc * 8;
        pBl = Blo + (size_t)trow * ldb + bn + tkc * 8;
    }
    uint32_t dA = sb + (uint32_t)trow * ROWB + tkc * 16;
    uint32_t dB = sb + S_BHI + (uint32_t)trow * ROWB + tkc * 16;

#define G2_ISSUE(k0, st) do { \
    _Pragma("unroll") \
    for (int i = 0; i < 4; i++) { \
        CPA16(dA + (st) + i * 4608,         pAh + (k0) + (size_t)i * 32 * lda); \
        CPA16(dA + (st) + S_ALO + i * 4608, pAl + (k0) + (size_t)i * 32 * lda); \
    } \
    _Pragma("unroll") \
    for (int i = 0; i < 2; i++) { \
        if (TRANSB) { \
            CPA16(dB + (st) + i * 4608,                   pBh + (k0) + (size_t)i * 32 * ldb); \
            CPA16(dB + (st) + (S_BLO-S_BHI) + i * 4608,   pBl + (k0) + (size_t)i * 32 * ldb); \
        } else { \
            CPA16(dB + (st) + i * 4608,                   pBh + (size_t)((k0) + i * 32) * ldb); \
            CPA16(dB + (st) + (S_BLO-S_BHI) + i * 4608,   pBl + (size_t)((k0) + i * 32) * ldb); \
        } \
    } \
    CPA_COMMIT(); \
} while (0)

    float acc[2][4][4];
#pragma unroll
    for (int i = 0; i < 2; i++)
#pragma unroll
        for (int f = 0; f < 4; f++)
#pragma unroll
            for (int r = 0; r < 4; r++) acc[i][f][r] = 0.f;

    int am = ((lane >> 3) & 1) * 8 + (lane & 7);
    int ak = (lane >> 4) * 8;
    int bnr = ((lane >> 4) & 1) * 8 + (lane & 7);
    int bkc = ((lane >> 3) & 1) * 8;
    int bkr = ((lane >> 3) & 1) * 8 + (lane & 7);
    int bnc = (lane >> 4) * 8;

    const int nch = K / 64;
    G2_ISSUE(0, 0);

    for (int ch = 0; ch < nch; ch++) {
        bool more = (ch + 1 < nch);
        if (more) G2_ISSUE((ch + 1) * 64, ((ch + 1) & 1) * STAGE);
        if (more) CPA_WAIT1(); else CPA_WAIT0();
        __syncthreads();

        uint32_t cur = (uint32_t)(ch & 1) * STAGE;
#pragma unroll
        for (int ks = 0; ks < 4; ks++) {
            int kk = ks * 16;
            uint32_t bh[4][2], bl[4][2];
#pragma unroll
            for (int g = 0; g < 2; g++) {
                uint32_t r[4];
                if (TRANSB) {
                    uint32_t off = cur + S_BHI + (uint32_t)(wn * 32 + g * 16 + bnr) * ROWB + (kk + bkc) * 2;
                    ldsm4(r, sb + off);
                    bh[g*2][0]=r[0]; bh[g*2][1]=r[1]; bh[g*2+1][0]=r[2]; bh[g*2+1][1]=r[3];
                    ldsm4(r, sb + off + (S_BLO - S_BHI));
                    bl[g*2][0]=r[0]; bl[g*2][1]=r[1]; bl[g*2+1][0]=r[2]; bl[g*2+1][1]=r[3];
                } else {
                    uint32_t off = cur + S_BHI + (uint32_t)(kk + bkr) * ROWB + (wn * 32 + g * 16 + bnc) * 2;
                    ldsm4t(r, sb + off);
                    bh[g*2][0]=r[0]; bh[g*2][1]=r[1]; bh[g*2+1][0]=r[2]; bh[g*2+1][1]=r[3];
                    ldsm4t(r, sb + off + (S_BLO - S_BHI));
                    bl[g*2][0]=r[0]; bl[g*2][1]=r[1]; bl[g*2+1][0]=r[2]; bl[g*2+1][1]=r[3];
                }
            }
            uint32_t ah[2][4], al[2][4];
#pragma unroll
            for (int i = 0; i < 2; i++) {
                uint32_t off = cur + (uint32_t)(wm * 32 + i * 16 + am) * ROWB + (kk + ak) * 2;
                ldsm4(ah[i], sb + off);
                ldsm4(al[i], sb + off + S_ALO);
            }
#pragma unroll
            for (int i = 0; i < 2; i++)
#pragma unroll
                for (int f = 0; f < 4; f++) {
                    mma16816(acc[i][f], ah[i], bh[f]);
                    mma16816(acc[i][f], ah[i], bl[f]);
                    mma16816(acc[i][f], al[i], bh[f]);
                }
        }
        __syncthreads();
    }

#pragma unroll
    for (int i = 0; i < 2; i++) {
#pragma unroll
        for (int f = 0; f < 4; f++) {
            int row = bm + wm * 32 + i * 16 + (lane >> 2);
            int col = bn + wn * 32 + f * 8 + (lane & 3) * 2;
            float2 bb = make_float2(0.f, 0.f);
            if (HASBIAS) bb = *(const float2*)&bias[(long)z * zBias + col];
            float2 v0, v1;
            v0.x = alpha * acc[i][f][0] + bb.x;
            v0.y = alpha * acc[i][f][1] + bb.y;
            v1.x = alpha * acc[i][f][2] + bb.x;
            v1.y = alpha * acc[i][f][3] + bb.y;
            size_t o0 = (size_t)z * zC + (size_t)row * ldc + col;
            size_t o1 = (size_t)z * zC + (size_t)(row + 8) * ldc + col;
            if (CSPLIT) {
                store_split2(Chi, Clo, o0, v0);
                store_split2(Chi, Clo, o1, v1);
            } else {
                *(float2*)&Cf[o0] = v0;
                *(float2*)&Cf[o1] = v1;
            }
        }
    }
#undef G2_ISSUE
}

// ================= qhat GEMM: A-resident, n-loop split across 2 blocks =========
#define Q_AHI 0
#define Q_ALO 18432
#define Q_B0  36864
#define Q_BSZ 18432
#define Q_EPI (Q_B0 + 2*Q_BSZ)
#define QH_TOTAL (Q_EPI + 128*66*4)

__global__ void __launch_bounds__(256, 2)
qhat2(const __nv_bfloat16* __restrict__ Ahi, const __nv_bfloat16* __restrict__ Alo,
      const __nv_bfloat16* __restrict__ WkH, const __nv_bfloat16* __restrict__ WkL)
{
    extern __shared__ __align__(16) char sm[];
    uint32_t sb = smem_u32(sm);

    int z = blockIdx.z;
    int bm = blockIdx.y * 128;
    int nt0 = blockIdx.x * 4;
    const __nv_bfloat16* BH = WkH + (size_t)z * Dd * Ee;
    const __nv_bfloat16* BL = WkL + (size_t)z * Dd * Ee;

    int tid = threadIdx.x;
    int lane = tid & 31;
    int wid = tid >> 5;
    int wm = wid & 3;
    int wn = wid >> 2;

    int trow = tid >> 3, tkc = tid & 7;
    {
        const __nv_bfloat16* pAh = Ahi + (size_t)(bm + trow) * Ee + z * Dd + tkc * 8;
        const __nv_bfloat16* pAl = Alo + (size_t)(bm + trow) * Ee + z * Dd + tkc * 8;
        uint32_t dA = sb + (uint32_t)trow * ROWB + tkc * 16;
#pragma unroll
        for (int i = 0; i < 4; i++) {
            CPA16(dA + i * 4608,         pAh + (size_t)i * 32 * Ee);
            CPA16(dA + Q_ALO + i * 4608, pAl + (size_t)i * 32 * Ee);
        }
    }
    const __nv_bfloat16* pBh = BH + (size_t)trow * Ee + tkc * 8;
    const __nv_bfloat16* pBl = BL + (size_t)trow * Ee + tkc * 8;
    uint32_t dB = sb + Q_B0 + (uint32_t)trow * ROWB + tkc * 16;

#define QB_ISSUE(nt, s) do { \
    _Pragma("unroll") \
    for (int i = 0; i < 2; i++) { \
        CPA16(dB + (s) * Q_BSZ + i * 4608,        pBh + (nt) * 64 + (size_t)i * 32 * Ee); \
        CPA16(dB + (s) * Q_BSZ + 9216 + i * 4608, pBl + (nt) * 64 + (size_t)i * 32 * Ee); \
    } \
    CPA_COMMIT(); \
} while (0)

    QB_ISSUE(nt0, 0);
    int am = ((lane >> 3) & 1) * 8 + (lane & 7);
    int ak = (lane >> 4) * 8;
    int bkr = ((lane >> 3) & 1) * 8 + (lane & 7);
    int bnc = (lane >> 4) * 8;
    int gid = lane >> 2, tig = lane & 3;
    float* ep = (float*)(sm + Q_EPI);        // [128][66]

    for (int j = 0; j < 4; j++) {
        int nt = nt0 + j;
        bool more = (j + 1 < 4);
        if (more) QB_ISSUE(nt + 1, (j + 1) & 1);
        if (more) CPA_WAIT1(); else CPA_WAIT0();
        __syncthreads();

        uint32_t bcur = Q_B0 + (uint32_t)(j & 1) * Q_BSZ;
        float acc[2][4][4];
#pragma unroll
        for (int i = 0; i < 2; i++)
#pragma unroll
            for (int f = 0; f < 4; f++)
#pragma unroll
                for (int r = 0; r < 4; r++) acc[i][f][r] = 0.f;

#pragma unroll
        for (int ks = 0; ks < 4; ks++) {
            int kk = ks * 16;
            uint32_t bh[4][2], bl[4][2];
#pragma unroll
            for (int g = 0; g < 2; g++) {
                uint32_t r[4];
                uint32_t off = bcur + (uint32_t)(kk + bkr) * ROWB + (wn * 32 + g * 16 + bnc) * 2;
                ldsm4t(r, sb + off);
                bh[g*2][0]=r[0]; bh[g*2][1]=r[1]; bh[g*2+1][0]=r[2]; bh[g*2+1][1]=r[3];
                ldsm4t(r, sb + off + 9216);
                bl[g*2][0]=r[0]; bl[g*2][1]=r[1]; bl[g*2+1][0]=r[2]; bl[g*2+1][1]=r[3];
            }
            uint32_t ah[2][4], al[2][4];
#pragma unroll
            for (int i = 0; i < 2; i++) {
                uint32_t off = (uint32_t)(wm * 32 + i * 16 + am) * ROWB + (kk + ak) * 2;
                ldsm4(ah[i], sb + off);
                ldsm4(al[i], sb + off + Q_ALO);
            }
#pragma unroll
            for (int i = 0; i < 2; i++)
#pragma unroll
                for (int f = 0; f < 4; f++) {
                    mma16816(acc[i][f], ah[i], bh[f]);
                    mma16816(acc[i][f], ah[i], bl[f]);
                    mma16816(acc[i][f], al[i], bh[f]);
                }
        }

        // ---- coalesced epilogue: stage fp32 tile, warps write whole rows ----
#pragma unroll
        for (int i = 0; i < 2; i++)
#pragma unroll
            for (int f = 0; f < 4; f++) {
                int rl = wm * 32 + i * 16 + gid;
                int cl = wn * 32 + f * 8 + tig * 2;
                ep[rl * 66 + cl]           = acc[i][f][0];
                ep[rl * 66 + cl + 1]       = acc[i][f][1];
                ep[(rl + 8) * 66 + cl]     = acc[i][f][2];
                ep[(rl + 8) * 66 + cl + 1] = acc[i][f][3];
            }
        __syncthreads();
#pragma unroll
        for (int r = 0; r < 16; r++) {
            int rl = wid + 8 * r;
            float2 v = *(float2*)&ep[rl * 66 + lane * 2];
            v.x *= 0.125f;
            v.y *= 0.125f;
            size_t o = (size_t)(bm + rl) * (Hh * Ee) + (size_t)z * Ee + nt * 64 + lane * 2;
            store_split2(g_qhatH, g_qhatL, o, v);
        }
        if (more) __syncthreads();   // last iteration: ep not reused, skip barrier
    }
#undef QB_ISSUE
}

// ================= fused segment attention, HMMA (R13 layout, conflict-free) ===
#define XROW   1040
#define F_XHI  0
#define F_XLO  33280
#define F_QHI  66560
#define F_QLO  74880
#define F_LGP  83200
#define F_LGS  91392
#define F_PHI  92544
#define F_PLO  93056
#define F_STM  93568
#define F_STZ  93600
#define F_STF  93632
#define SMEM_FA 93664

__global__ void __launch_bounds__(256)
fused_attn_kernel(const float* __restrict__ X)
{
    extern __shared__ __align__(16) char fsm[];
    uint32_t sb = smem_u32(fsm);

    int b = blockIdx.x;
    int t = threadIdx.x;
    int w = t >> 5, lane = t & 31;
    int gid = lane >> 2, tig = lane & 3;
    int s0 = g_segstart[b], e0 = g_segstart[b + 1];

    float* stm = (float*)(fsm + F_STM);
    float* stz = (float*)(fsm + F_STZ);
    float* stf = (float*)(fsm + F_STF);
    float* lgs = (float*)(fsm + F_LGS);
    float* lgp = (float*)(fsm + F_LGP);

    {
        const __nv_bfloat16* qh = g_qhatH + (size_t)b * (Hh * Ee);
        const __nv_bfloat16* ql = g_qhatL + (size_t)b * (Hh * Ee);
#pragma unroll
        for (int i = 0; i < 4; i++) {
            int idx = t + 256 * i;
            int which = idx >> 9;
            int j = idx & 511;
            int h = j >> 6, piece = j & 63;
            const __nv_bfloat16* src = (which ? ql : qh) + h * Ee + piece * 8;
            uint32_t dst = sb + (which ? F_QLO : F_QHI) + (uint32_t)h * XROW + piece * 16;
            CPA16(dst, src);
        }
        CPA_COMMIT();
    }
    if (t < 8) { stm[t] = -1e30f; stz[t] = 0.f; }

    int am  = ((lane >> 3) & 1) * 8 + (lane & 7);
    int ak  = (lane >> 4) * 8;
    int bkr = ((lane >> 3) & 1) * 8 + (lane & 7);
    int bnc = (lane >> 4) * 8;
    int qrow = lane & 7;
    int qc8  = (lane >> 3) * 8;

    float acc[4][4];
#pragma unroll
    for (int mt = 0; mt < 4; mt++)
#pragma unroll
        for (int r = 0; r < 4; r++) acc[mt][r] = 0.f;

    for (int base = s0; base < e0; base += 32) {
        int cnt = min(32, e0 - base);

#pragma unroll
        for (int i = 0; i < 16; i++) {
            int flat = t + 256 * i;
            int node = flat >> 7, c4 = flat & 127;
            float4 v = make_float4(0.f, 0.f, 0.f, 0.f);
            if (node < cnt)
                v = *(const float4*)&X[(size_t)(base + node) * Ee + c4 * 4];
            uint2 hi, lo;
            split4(v, hi, lo);
            uint32_t off = (uint32_t)node * XROW + (uint32_t)c4 * 8;
            *(uint2*)(fsm + F_XHI + off) = hi;
            *(uint2*)(fsm + F_XLO + off) = lo;
        }
        CPA_WAIT0();
        __syncthreads();

        {
            float lg[2][4];
#pragma unroll
            for (int m = 0; m < 2; m++)
#pragma unroll
                for (int r = 0; r < 4; r++) lg[m][r] = 0.f;

            int ks0 = w * 64;
#pragma unroll
            for (int kb = 0; kb < 2; kb++) {
                int kbase = ks0 + kb * 32;
                uint32_t rq[4];
                uint32_t qoff = (uint32_t)qrow * XROW + (uint32_t)(kbase + qc8) * 2;
                uint32_t bqh[2][2], bql[2][2];
                ldsm4(rq, sb + F_QHI + qoff);
                bqh[0][0]=rq[0]; bqh[0][1]=rq[1]; bqh[1][0]=rq[2]; bqh[1][1]=rq[3];
                ldsm4(rq, sb + F_QLO + qoff);
                bql[0][0]=rq[0]; bql[0][1]=rq[1]; bql[1][0]=rq[2]; bql[1][1]=rq[3];
#pragma unroll
                for (int ks = 0; ks < 2; ks++) {
                    int kk = kbase + ks * 16;
                    uint32_t ah[2][4], al[2][4];
#pragma unroll
                    for (int m = 0; m < 2; m++) {
                        uint32_t aoff = (uint32_t)(m * 16 + am) * XROW + (uint32_t)(kk + ak) * 2;
                        ldsm4(ah[m], sb + F_XHI + aoff);
                        ldsm4(al[m], sb + F_XLO + aoff);
                    }
#pragma unroll
                    for (int m = 0; m < 2; m++) {
                        mma16816(lg[m], ah[m], bqh[ks]);
                        mma16816(lg[m], ah[m], bql[ks]);
                        mma16816(lg[m], al[m], bqh[ks]);
                    }
                }
            }
            float* lp = lgp + w * 256;
#pragma unroll
            for (int m = 0; m < 2; m++) {
                lp[(m * 16 + gid) * 8 + 2 * tig]     = lg[m][0];
                lp[(m * 16 + gid) * 8 + 2 * tig + 1] = lg[m][1];
                lp[(m * 16 + gid + 8) * 8 + 2 * tig]     = lg[m][2];
                lp[(m * 16 + gid + 8) * 8 + 2 * tig + 1] = lg[m][3];
            }
        }
        __syncthreads();

        {
            float s = 0.f;
#pragma unroll
            for (int w2 = 0; w2 < 8; w2++) s += lgp[w2 * 256 + t];
            lgs[(t >> 3) * 9 + (t & 7)] = s;
        }
        __syncthreads();

        {
            float v = (lane < cnt) ? lgs[lane * 9 + w] : -1e30f;
            float mx = v;
#pragma unroll
            for (int o = 16; o; o >>= 1) mx = fmaxf(mx, __shfl_xor_sync(0xffffffffu, mx, o));
            float mo = stm[w];
            float mn = fmaxf(mo, mx);
            float p = (lane < cnt) ? __expf(v - mn) : 0.f;
            __nv_bfloat16 ph = __float2bfloat16(p);
            __nv_bfloat16 pl = __float2bfloat16(p - __bfloat162float(ph));
            ((__nv_bfloat16*)(fsm + F_PHI))[lane * 8 + w] = ph;
            ((__nv_bfloat16*)(fsm + F_PLO))[lane * 8 + w] = pl;
            float ssum = p;
#pragma unroll
            for (int o = 16; o; o >>= 1) ssum += __shfl_xor_sync(0xffffffffu, ssum, o);
            if (lane == 0) {
                float f = __expf(mo - mn);
                stf[w] = f;
                stm[w] = mn;
                stz[w] = stz[w] * f + ssum;
            }
        }
        __syncthreads();

        {
            float f0 = stf[2 * tig];
            float f1 = stf[2 * tig + 1];
#pragma unroll
            for (int mt = 0; mt < 4; mt++) {
                acc[mt][0] *= f0; acc[mt][1] *= f1;
                acc[mt][2] *= f0; acc[mt][3] *= f1;
            }
            uint32_t rp[4];
            uint32_t bph[2][2], bpl[2][2];
            ldsm4t(rp, sb + F_PHI + (uint32_t)lane * 16);
            bph[0][0]=rp[0]; bph[0][1]=rp[1]; bph[1][0]=rp[2]; bph[1][1]=rp[3];
            ldsm4t(rp, sb + F_PLO + (uint32_t)lane * 16);
            bpl[0][0]=rp[0]; bpl[0][1]=rp[1]; bpl[1][0]=rp[2]; bpl[1][1]=rp[3];

#pragma unroll
            for (int ks = 0; ks < 2; ks++) {
#pragma unroll
                for (int mt = 0; mt < 4; mt++) {
                    uint32_t aoff = (uint32_t)(ks * 16 + bkr) * XROW
                                  + (uint32_t)(w * 64 + mt * 16 + bnc) * 2;
                    uint32_t ra[4], rl[4];
                    ldsm4t(ra, sb + F_XHI + aoff);
                    ldsm4t(rl, sb + F_XLO + aoff);
                    uint32_t ah2[4] = {ra[0], ra[2], ra[1], ra[3]};
                    uint32_t al2[4] = {rl[0], rl[2], rl[1], rl[3]};
                    mma16816(acc[mt], ah2, bph[ks]);
                    mma16816(acc[mt], al2, bph[ks]);
                    mma16816(acc[mt], ah2, bpl[ks]);
                }
            }
        }
        __syncthreads();
    }

    float rz0 = 1.f / stz[2 * tig];
    float rz1 = 1.f / stz[2 * tig + 1];
    float* fxw = (float*)(fsm + F_XHI);
#pragma unroll
    for (int mt = 0; mt < 4; mt++) {
        int col = w * 64 + mt * 16;
        fxw[(2 * tig) * 520 + col + gid]         = acc[mt][0] * rz0;
        fxw[(2 * tig + 1) * 520 + col + gid]     = acc[mt][1] * rz1;
        fxw[(2 * tig) * 520 + col + 8 + gid]     = acc[mt][2] * rz0;
        fxw[(2 * tig + 1) * 520 + col + 8 + gid] = acc[mt][3] * rz1;
    }
    __syncthreads();
#pragma unroll
    for (int i = 0; i < 8; i++) {
        int idx = t + 256 * i;
        int h = idx >> 8, cp = (idx & 255) * 2;
        float2 v = make_float2(fxw[h * 520 + cp], fxw[h * 520 + cp + 1]);
        store_split2(g_xwH, g_xwL, ((size_t)b * Hh + h) * Ee + cp, v);
    }
}

// ---------------- LayerNorm ----------------
__global__ void __launch_bounds__(256) ln_kernel(const float* __restrict__ lng,
                                                 const float* __restrict__ lnb,
                                                 float* __restrict__ out)
{
    int b = blockIdx.x;
    int t = threadIdx.x;
    float v0 = g_outbuf[(long)b * Ee + t];
    float v1 = g_outbuf[(long)b * Ee + t + 256];
    float s = v0 + v1;
    float q = v0 * v0 + v1 * v1;
#pragma unroll
    for (int o = 16; o; o >>= 1) {
        s += __shfl_xor_sync(0xffffffffu, s, o);
        q += __shfl_xor_sync(0xffffffffu, q, o);
    }
    __shared__ float ss[8], qs[8];
    __shared__ float mu_s, r_s;
    int wid = t >> 5, lane = t & 31;
    if (lane == 0) { ss[wid] = s; qs[wid] = q; }
    __syncthreads();
    if (t == 0) {
        float S = 0.f, Q = 0.f;
#pragma unroll
        for (int i = 0; i < 8; i++) { S += ss[i]; Q += qs[i]; }
        float mu = S / (float)Ee;
        float var = Q / (float)Ee - mu * mu;
        mu_s = mu;
        r_s = 1.f / sqrtf(var + 1e-5f);
    }
    __syncthreads();
    float mu = mu_s, r = r_s;
    out[(long)b * Ee + t]       = (v0 - mu) * r * lng[t]       + lnb[t];
    out[(long)b * Ee + t + 256] = (v1 - mu) * r * lng[t + 256] + lnb[t + 256];
}

// ---------------- launch ----------------
extern "C" void kernel_launch(void* const* d_in, const int* in_sizes, int n_in,
                              void* d_out, int out_size)
{
    (void)in_sizes; (void)n_in; (void)out_size;
    const float* X        = (const float*)d_in[0];
    const float* scaffold = (const float*)d_in[1];
    const float* Wq       = (const float*)d_in[2];
    const float* bq       = (const float*)d_in[3];
    const float* Wk       = (const float*)d_in[4];
    const float* Wv       = (const float*)d_in[6];
    const float* bv       = (const float*)d_in[7];
    const float* ipw      = (const float*)d_in[8];
    const float* ipb      = (const float*)d_in[9];
    const float* mow      = (const float*)d_in[10];
    const float* mob      = (const float*)d_in[11];
    const float* ow       = (const float*)d_in[12];
    const float* ob       = (const float*)d_in[13];
    const float* lng      = (const float*)d_in[14];
    const float* lnb      = (const float*)d_in[15];
    const int*   batch    = (const int*)d_in[16];

    void* p;
    cudaGetSymbolAddress(&p, g_AcatH);   __nv_bfloat16* AcatH = (__nv_bfloat16*)p;
    cudaGetSymbolAddress(&p, g_AcatL);   __nv_bfloat16* AcatL = (__nv_bfloat16*)p;
    cudaGetSymbolAddress(&p, g_BcatH);   __nv_bfloat16* BcatH = (__nv_bfloat16*)p;
    cudaGetSymbolAddress(&p, g_BcatL);   __nv_bfloat16* BcatL = (__nv_bfloat16*)p;
    cudaGetSymbolAddress(&p, g_scafH);   __nv_bfloat16* scafH = (__nv_bfloat16*)p;
    cudaGetSymbolAddress(&p, g_scafL);   __nv_bfloat16* scafL = (__nv_bfloat16*)p;
    cudaGetSymbolAddress(&p, g_WeffH);   __nv_bfloat16* WeffH = (__nv_bfloat16*)p;
    cudaGetSymbolAddress(&p, g_WeffL);   __nv_bfloat16* WeffL = (__nv_bfloat16*)p;
    cudaGetSymbolAddress(&p, g_qqH);     __nv_bfloat16* qqH   = (__nv_bfloat16*)p;
    cudaGetSymbolAddress(&p, g_qqL);     __nv_bfloat16* qqL   = (__nv_bfloat16*)p;
    cudaGetSymbolAddress(&p, g_xwH);     __nv_bfloat16* xwH   = (__nv_bfloat16*)p;
    cudaGetSymbolAddress(&p, g_xwL);     __nv_bfloat16* xwL   = (__nv_bfloat16*)p;
    cudaGetSymbolAddress(&p, g_pooledH); __nv_bfloat16* plH   = (__nv_bfloat16*)p;
    cudaGetSymbolAddress(&p, g_pooledL); __nv_bfloat16* plL   = (__nv_bfloat16*)p;
    cudaGetSymbolAddress(&p, g_beff);    float* beff  = (float*)p;
    cudaGetSymbolAddress(&p, g_outbuf);  float* outbuf = (float*)p;

    cudaFuncSetAttribute(tcgemm2<false, false, true>,
                         cudaFuncAttributeMaxDynamicSharedMemorySize, SM2_TOTAL);
    cudaFuncSetAttribute(tcgemm2<true, true, true>,
                         cudaFuncAttributeMaxDynamicSharedMemorySize, SM2_TOTAL);
    cudaFuncSetAttribute(tcgemm2<true, true, false>,
                         cudaFuncAttributeMaxDynamicSharedMemorySize, SM2_TOTAL);
    cudaFuncSetAttribute(qhat2,
                         cudaFuncAttributeMaxDynamicSharedMemorySize, QH_TOTAL);
    cudaFuncSetAttribute(fused_attn_kernel,
                         cudaFuncAttributeMaxDynamicSharedMemorySize, SMEM_FA);

    // ALL independent preprocessing in one launch
    prep<<<4800, 256>>>(ipw, ow, Wq, Wk, Wv, mow, scaffold, batch,
                        ipb, bq, bv, mob, ob);

    // fold: Weff[z] = Acat[z] @ Bcat[z] (NN), write hi/lo
    tcgemm2<false, false, true><<<dim3(8, 4, 4), 256, SM2_TOTAL>>>(
        AcatH, AcatL, BcatH, BcatL, nullptr, WeffH, WeffL, nullptr,
        512, 512, 512, 512, (long)EE, (long)EE, (long)EE, 0, 1.f);

    // qq = scaffold @ Wq_eff^T + bq_eff (NT), write hi/lo
    tcgemm2<true, true, true><<<dim3(8, 32, 1), 256, SM2_TOTAL>>>(
        scafH, scafL, WeffH, WeffL, nullptr, qqH, qqL, beff,
        512, Ee, Ee, Ee, 0, 0, 0, 0, 1.f);

    // qhat (A-resident, n-split x2, pipelined, coalesced epilogue; writes hi/lo)
    qhat2<<<dim3(2, 32, 8), 256, QH_TOTAL>>>(qqH, qqL, WeffH + EE, WeffL + EE);

    fused_attn_kernel<<<Bb, 256, SMEM_FA>>>(X);

    // pooled = xw @ Wv_eff_h^T + bv_eff (NT), write hi/lo
    tcgemm2<true, true, true><<<dim3(1, 32, 8), 256, SM2_TOTAL>>>(
        xwH, xwL, WeffH + 2 * EE, WeffL + 2 * EE, nullptr, plH, plL, beff + Ee,
        512, Hh * Ee, Ee, Ee, (long)Ee, (long)Dd * Ee, (long)Dd, Dd, 1.f);

    // out = pooled @ Wo_eff^T + bo_eff (NT), write fp32
    tcgemm2<true, true, false><<<dim3(8, 32, 1), 256, SM2_TOTAL>>>(
        plH, plL, WeffH + 3 * EE, WeffL + 3 * EE, outbuf, nullptr, nullptr, beff + 2 * Ee,
        512, Ee, Ee, Ee, 0, 0, 0, 0, 1.f);

    ln_kernel<<<Bb, 256>>>(lng, lnb, (float*)d_out);
}